// round 15
// baseline (speedup 1.0000x reference)
#include <cuda_runtime.h>
#include <cuda_bf16.h>
#include <cstdint>

// Gather: out[g][row][j*32+k] = in[row][g*512 + j*64 + k]
//   out flat float4 idx i: g=i>>20, row=(i>>6)&16383, v=i&63
//   src (float4 units) = row*1024 + g*128 + (v>>3)*16 + (v&7)
//
// TERMINAL KERNEL (R10; best measured 44.128us, best 2-run avg ~44.6us).
//   * front-batched MLP=4 per thread at regs=30 -> ~84% occupancy,
//   * compile-time-constant grid stride (2^21),
//   * linear grid-stride mapping.
// 14 rounds established the structural roofline: irreducible 256 MiB/replay
// (128 MiB half-dense reads + 128 MiB dense writes, zero reuse) served at
// ~5.9 TB/s effective. Falsified levers: MLP 8-32 (ptxas re-serializes or
// regresses), 256-bit accesses, software pipelining, every L2
// eviction-class residency scheme (clean pin / no-alloc / dirty pin),
// concurrency remaps, and block-granularity tuning — all within the
// +-0.5us noise band or worse.

#define GRID_BLOCKS 8192u
#define STRIDE      (GRID_BLOCKS * 256u)   // 2^21 float4s

__global__ void __launch_bounds__(256)
fuse_slice_cat_kernel(const float4* __restrict__ in, float4* __restrict__ out)
{
    const unsigned int i0 = blockIdx.x * 256u + threadIdx.x;

    unsigned int idx[4];
    unsigned int srcI[4];

    #pragma unroll
    for (int it = 0; it < 4; ++it) {
        unsigned int i   = i0 + (unsigned)it * STRIDE;
        unsigned int g   = i >> 20;
        unsigned int row = (i >> 6) & 16383u;
        unsigned int v   = i & 63u;
        idx[it]  = i;
        srcI[it] = row * 1024u + g * 128u + (v >> 3) * 16u + (v & 7u);
    }

    float4 r[4];
    #pragma unroll
    for (int it = 0; it < 4; ++it)      // 4 loads in flight before any store
        r[it] = in[srcI[it]];

    #pragma unroll
    for (int it = 0; it < 4; ++it)
        out[idx[it]] = r[it];
}

extern "C" void kernel_launch(void* const* d_in, const int* in_sizes, int n_in,
                              void* d_out, int out_size)
{
    const float4* in  = (const float4*)d_in[0];
    float4*       out = (float4*)d_out;

    fuse_slice_cat_kernel<<<GRID_BLOCKS, 256>>>(in, out);
}